// round 16
// baseline (speedup 1.0000x reference)
#include <cuda_runtime.h>
#include <cstdint>

// ---------------------------------------------------------------------------
// AdjGenerator: adj = (mean_h sigmoid(log(relu(Wg·PE)+1e-6) + (q·kT)/32) > 0.5)
// N = M = 2048, D = 1024, EMB = 64, HEADS = 16
// R16: GEMM re-tiled to 256thr/128x128 with __launch_bounds__(256,2):
//      32 warps/SM (8/SMSP) to cover the LDS->fma latency gap (fma 65%->85%).
// ---------------------------------------------------------------------------

#define NDIM 2048
#define MDIM 2048
#define DDIM 1024
#define EMB  64
#define HEADS 16

__device__ float g_q[NDIM * DDIM];
__device__ float g_k[MDIM * DDIM];
__device__ float g_aff[NDIM * MDIM];

typedef unsigned long long ull;

// ---- packed f32x2 helpers (Blackwell FFMA2, PTX-only) ---------------------
__device__ __forceinline__ ull dup2(float v) {
    ull r;
    asm("mov.b64 %0, {%1, %1};" : "=l"(r) : "f"(v));
    return r;
}
__device__ __forceinline__ void fma2(ull& d, ull a, ull b) {
    asm("fma.rn.f32x2 %0, %1, %2, %0;" : "+l"(d) : "l"(a), "l"(b));
}
__device__ __forceinline__ float2 unpack2(ull v) {
    float2 f;
    asm("mov.b64 {%0, %1}, %2;" : "=f"(f.x), "=f"(f.y) : "l"(v));
    return f;
}
__device__ __forceinline__ uint32_t smem_u32(const void* p) {
    uint32_t a;
    asm("{ .reg .u64 t; cvta.to.shared.u64 t, %1; cvt.u32.u64 %0, t; }" : "=r"(a) : "l"(p));
    return a;
}
__device__ __forceinline__ void cp_async16(uint32_t saddr, const void* gptr) {
    asm volatile("cp.async.cg.shared.global [%0], [%1], 16;"
                 :: "r"(saddr), "l"(gptr) : "memory");
}
#define CP_COMMIT() asm volatile("cp.async.commit_group;" ::: "memory")
#define CP_WAIT(n)  asm volatile("cp.async.wait_group %0;" :: "n"(n) : "memory")

// ---------------------------------------------------------------------------
// SGEMM NT: C[r,c] = scale * sum_d A[r,d]*B[c,d] + bias[c]
// 256 threads, BM=128, BN=128, BK=16, 8 rows x 8 cols per thread.
// Row-packed f32x2 accumulators (A pairs free via LDS.128); B float smem,
// reg-side dup; conflict-free B cols {tx*4, 64+tx*4}. Double-buffered.
// 2 CTAs/SM (launch_bounds cap 128 regs) -> 8 warps/SMSP latency hiding.
// ---------------------------------------------------------------------------
#define BM 128
#define BN 128
#define BK 16
#define BH 64    /* BN/2 */
#define NCHUNK (DDIM / BK)

__global__ void __launch_bounds__(256, 2)
gemm_nt_kernel(const float* __restrict__ A0, const float* __restrict__ B0,
               const float* __restrict__ bias0,
               const float* __restrict__ A1, const float* __restrict__ B1,
               const float* __restrict__ bias1,
               int Ncols, float scale, int outsel)
{
    const float* A;
    const float* B;
    const float* bias;
    float* C;
    if (outsel == 0) {
        if (blockIdx.z == 0) { A = A0; B = B0; bias = bias0; C = g_q; }
        else                 { A = A1; B = B1; bias = bias1; C = g_k; }
    } else {
        A = g_q; B = g_k; bias = nullptr; C = g_aff;
    }

    const int K = DDIM;

    __shared__ float As[2][BK][BM + 4];   // 16.9 KB
    __shared__ float Bs[2][BK][BN + 4];   // 16.9 KB

    const int tid = threadIdx.x;
    const int tx = tid & 15;        // 0..15 -> col pair {tx*4, 64+tx*4}
    const int ty = tid >> 4;        // 0..15 -> 8-row block
    const int row0 = blockIdx.y * BM;
    const int col0 = blockIdx.x * BN;

    const float* Abase = A + (size_t)row0 * K;
    const float* Bbase = B + (size_t)col0 * K;

    // fill: A 512 float4 slots (2/thread), B 512 slots (2/thread)
    const int ar0 = tid >> 2,          ac0 = (tid & 3) * 4;         // rows 0..63
    const int ar1 = (tid + 256) >> 2,  ac1 = ((tid + 256) & 3) * 4; // rows 64..127

    float4 av0 = *(const float4*)&Abase[(size_t)ar0 * K + ac0];
    float4 av1 = *(const float4*)&Abase[(size_t)ar1 * K + ac1];
    float4 bv0 = *(const float4*)&Bbase[(size_t)ar0 * K + ac0];
    float4 bv1 = *(const float4*)&Bbase[(size_t)ar1 * K + ac1];

    As[0][ac0 + 0][ar0] = av0.x; As[0][ac0 + 1][ar0] = av0.y;
    As[0][ac0 + 2][ar0] = av0.z; As[0][ac0 + 3][ar0] = av0.w;
    As[0][ac1 + 0][ar1] = av1.x; As[0][ac1 + 1][ar1] = av1.y;
    As[0][ac1 + 2][ar1] = av1.z; As[0][ac1 + 3][ar1] = av1.w;
    Bs[0][ac0 + 0][ar0] = bv0.x; Bs[0][ac0 + 1][ar0] = bv0.y;
    Bs[0][ac0 + 2][ar0] = bv0.z; Bs[0][ac0 + 3][ar0] = bv0.w;
    Bs[0][ac1 + 0][ar1] = bv1.x; Bs[0][ac1 + 1][ar1] = bv1.y;
    Bs[0][ac1 + 2][ar1] = bv1.z; Bs[0][ac1 + 3][ar1] = bv1.w;
    __syncthreads();

    ull c2[4][8];   // [row-pair][col]
#pragma unroll
    for (int i = 0; i < 4; i++)
#pragma unroll
        for (int j = 0; j < 8; j++) c2[i][j] = 0ull;

    int s = 0;
    for (int c = 0; c < NCHUNK; c++) {
        const int kc = (c + 1) * BK;
        if (c + 1 < NCHUNK) {
            av0 = *(const float4*)&Abase[(size_t)ar0 * K + kc + ac0];
            av1 = *(const float4*)&Abase[(size_t)ar1 * K + kc + ac1];
            bv0 = *(const float4*)&Bbase[(size_t)ar0 * K + kc + ac0];
            bv1 = *(const float4*)&Bbase[(size_t)ar1 * K + kc + ac1];
        }
#pragma unroll
        for (int k = 0; k < BK; k++) {
            // A: 8 adjacent rows = 4 packed pairs, 2x broadcast LDS.128
            ulonglong2 aA = *(const ulonglong2*)&As[s][k][ty * 8];
            ulonglong2 aB = *(const ulonglong2*)&As[s][k][ty * 8 + 4];
            ull a2[4] = { aA.x, aA.y, aB.x, aB.y };
            // B: 8 float cols, 2 conflict-free LDS.128 (16B lane stride)
            float4 f0 = *(const float4*)&Bs[s][k][tx * 4];
            float4 f1 = *(const float4*)&Bs[s][k][BH + tx * 4];
            ull b2[8];
            b2[0] = dup2(f0.x); b2[1] = dup2(f0.y); b2[2] = dup2(f0.z); b2[3] = dup2(f0.w);
            b2[4] = dup2(f1.x); b2[5] = dup2(f1.y); b2[6] = dup2(f1.z); b2[7] = dup2(f1.w);
#pragma unroll
            for (int i = 0; i < 4; i++) {
#pragma unroll
                for (int j = 0; j < 8; j++) fma2(c2[i][j], a2[i], b2[j]);
            }
        }
        if (c + 1 < NCHUNK) {
            const int t = s ^ 1;
            As[t][ac0 + 0][ar0] = av0.x; As[t][ac0 + 1][ar0] = av0.y;
            As[t][ac0 + 2][ar0] = av0.z; As[t][ac0 + 3][ar0] = av0.w;
            As[t][ac1 + 0][ar1] = av1.x; As[t][ac1 + 1][ar1] = av1.y;
            As[t][ac1 + 2][ar1] = av1.z; As[t][ac1 + 3][ar1] = av1.w;
            Bs[t][ac0 + 0][ar0] = bv0.x; Bs[t][ac0 + 1][ar0] = bv0.y;
            Bs[t][ac0 + 2][ar0] = bv0.z; Bs[t][ac0 + 3][ar0] = bv0.w;
            Bs[t][ac1 + 0][ar1] = bv1.x; Bs[t][ac1 + 1][ar1] = bv1.y;
            Bs[t][ac1 + 2][ar1] = bv1.z; Bs[t][ac1 + 3][ar1] = bv1.w;
            __syncthreads();
            s = t;
        }
    }

    // epilogue: row pairs; per row, float4 per column half
    float4 bv_lo, bv_hi;
    if (bias) {
        bv_lo = *(const float4*)&bias[col0 + tx * 4];
        bv_hi = *(const float4*)&bias[col0 + BH + tx * 4];
    }
#pragma unroll
    for (int i2 = 0; i2 < 4; i2++) {
        size_t r = (size_t)(row0 + ty * 8 + 2 * i2);
        float* rlo = C + r * (size_t)Ncols + col0;
        float* rhi = rlo + Ncols;
        float2 p0 = unpack2(c2[i2][0]);
        float2 p1 = unpack2(c2[i2][1]);
        float2 p2 = unpack2(c2[i2][2]);
        float2 p3 = unpack2(c2[i2][3]);
        float2 p4 = unpack2(c2[i2][4]);
        float2 p5 = unpack2(c2[i2][5]);
        float2 p6 = unpack2(c2[i2][6]);
        float2 p7 = unpack2(c2[i2][7]);
        float4 lo0, lo1, hi0, hi1;
        if (bias) {
            lo0 = make_float4(p0.x * scale + bv_lo.x, p1.x * scale + bv_lo.y,
                              p2.x * scale + bv_lo.z, p3.x * scale + bv_lo.w);
            hi0 = make_float4(p0.y * scale + bv_lo.x, p1.y * scale + bv_lo.y,
                              p2.y * scale + bv_lo.z, p3.y * scale + bv_lo.w);
            lo1 = make_float4(p4.x * scale + bv_hi.x, p5.x * scale + bv_hi.y,
                              p6.x * scale + bv_hi.z, p7.x * scale + bv_hi.w);
            hi1 = make_float4(p4.y * scale + bv_hi.x, p5.y * scale + bv_hi.y,
                              p6.y * scale + bv_hi.z, p7.y * scale + bv_hi.w);
        } else {
            lo0 = make_float4(p0.x * scale, p1.x * scale, p2.x * scale, p3.x * scale);
            hi0 = make_float4(p0.y * scale, p1.y * scale, p2.y * scale, p3.y * scale);
            lo1 = make_float4(p4.x * scale, p5.x * scale, p6.x * scale, p7.x * scale);
            hi1 = make_float4(p4.y * scale, p5.y * scale, p6.y * scale, p7.y * scale);
        }
        *(float4*)&rlo[tx * 4]      = lo0;
        *(float4*)&rlo[BH + tx * 4] = lo1;
        *(float4*)&rhi[tx * 4]      = hi0;
        *(float4*)&rhi[BH + tx * 4] = hi1;
    }
}

// ---------------------------------------------------------------------------
// Pos-gate stream + fused epilogue (R15 verified, ~214us).
// ---------------------------------------------------------------------------
#define RDEPTH 8

__global__ void __launch_bounds__(256, 2)
pos_epilogue_kernel(const float* __restrict__ PE, const float* __restrict__ Wg_w,
                    const float* __restrict__ Wg_b, float* __restrict__ out)
{
    __shared__ ull sh_wg2[EMB][HEADS];          // 8 KB
    __shared__ float sh_b[HEADS];
    __shared__ ull ring[RDEPTH * 256 * 2];      // 32 KB: stage stride 4096 B

    const int tid = threadIdx.x;
    for (int idx = tid; idx < EMB * HEADS; idx += 256) {
        int e = idx >> 4, h = idx & 15;
        sh_wg2[e][h] = dup2(Wg_w[h * EMB + e]);
    }
    if (tid < HEADS) sh_b[tid] = Wg_b[tid];
    __syncthreads();

    const int n = blockIdx.y;
    const int m = blockIdx.x * 1024 + tid * 4;

    const char* pe = (const char*)(PE + (size_t)n * MDIM + m);
    const size_t PLANE = (size_t)NDIM * MDIM * 4;   // bytes

    const uint32_t myslot = smem_u32(&ring[tid * 2]);

    ull acc[HEADS][2];
#pragma unroll
    for (int h = 0; h < HEADS; h++) { acc[h][0] = 0ull; acc[h][1] = 0ull; }

#pragma unroll
    for (int i = 0; i < RDEPTH; i++) {
        cp_async16(myslot + i * 4096, pe + (size_t)i * PLANE);
        CP_COMMIT();
    }

    ull wA[8], wB[8];
    {
        const ulonglong2* wr = (const ulonglong2*)&sh_wg2[0][0];
        ulonglong2 t0 = wr[0], t1 = wr[1], t2 = wr[2], t3 = wr[3];
        wA[0] = t0.x; wA[1] = t0.y; wA[2] = t1.x; wA[3] = t1.y;
        wA[4] = t2.x; wA[5] = t2.y; wA[6] = t3.x; wA[7] = t3.y;
    }

#pragma unroll 8
    for (int e = 0; e < EMB; e++) {
        CP_WAIT(RDEPTH - 1);
        ull pvx, pvy;
        asm volatile("ld.shared.v2.u64 {%0, %1}, [%2];"
                     : "=l"(pvx), "=l"(pvy) : "r"(myslot + (e & 7) * 4096));

        int en_ = e + RDEPTH;
        if (en_ < EMB) cp_async16(myslot + (e & 7) * 4096, pe + (size_t)en_ * PLANE);
        CP_COMMIT();

        {
            const ulonglong2* wr = (const ulonglong2*)&sh_wg2[e][8];
            ulonglong2 t0 = wr[0], t1 = wr[1], t2 = wr[2], t3 = wr[3];
            wB[0] = t0.x; wB[1] = t0.y; wB[2] = t1.x; wB[3] = t1.y;
            wB[4] = t2.x; wB[5] = t2.y; wB[6] = t3.x; wB[7] = t3.y;
        }
#pragma unroll
        for (int h = 0; h < 8; h++) {
            fma2(acc[h][0], wA[h], pvx);
            fma2(acc[h][1], wA[h], pvy);
        }
        if (e + 1 < EMB) {
            const ulonglong2* wr = (const ulonglong2*)&sh_wg2[e + 1][0];
            ulonglong2 t0 = wr[0], t1 = wr[1], t2 = wr[2], t3 = wr[3];
            wA[0] = t0.x; wA[1] = t0.y; wA[2] = t1.x; wA[3] = t1.y;
            wA[4] = t2.x; wA[5] = t2.y; wA[6] = t3.x; wA[7] = t3.y;
        }
#pragma unroll
        for (int h = 0; h < 8; h++) {
            fma2(acc[8 + h][0], wB[h], pvx);
            fma2(acc[8 + h][1], wB[h], pvy);
        }
    }

    const float4 av = *(const float4*)&g_aff[(size_t)n * MDIM + m];
    const float L2E = 1.4426950408889634f;
    float E[4];
    E[0] = exp2f(-av.x * L2E);
    E[1] = exp2f(-av.y * L2E);
    E[2] = exp2f(-av.z * L2E);
    E[3] = exp2f(-av.w * L2E);

    float w[HEADS][4];
#pragma unroll
    for (int h = 0; h < HEADS; h++) {
        float bh = sh_b[h];
        float2 p0 = unpack2(acc[h][0]);
        float2 p1 = unpack2(acc[h][1]);
        w[h][0] = fmaxf(p0.x + bh, 0.f) + 1e-6f;
        w[h][1] = fmaxf(p0.y + bh, 0.f) + 1e-6f;
        w[h][2] = fmaxf(p1.x + bh, 0.f) + 1e-6f;
        w[h][3] = fmaxf(p1.y + bh, 0.f) + 1e-6f;
    }

    float4 o;
    float* op = &o.x;
#pragma unroll
    for (int j = 0; j < 4; j++) {
        float Ej = E[j];
        float s = 0.f;
#pragma unroll
        for (int p = 0; p < 8; p++) {
            float a = w[2 * p][j], b = w[2 * p + 1][j];
            float ab = a * b;
            float num = fmaf(Ej, a + b, 2.0f * ab);
            float den = fmaf(a + Ej, b, (a + Ej) * Ej);
            s += __fdividef(num, den);
        }
        op[j] = (s > 8.0f) ? 1.0f : 0.0f;
    }
    *(float4*)&out[(size_t)n * MDIM + m] = o;
}

// ---------------------------------------------------------------------------
extern "C" void kernel_launch(void* const* d_in, const int* in_sizes, int n_in,
                              void* d_out, int out_size)
{
    (void)in_sizes; (void)n_in; (void)out_size;
    const float* ref_feat = (const float*)d_in[0];
    const float* sup_feat = (const float*)d_in[1];
    const float* PE       = (const float*)d_in[2];
    const float* Wg_w     = (const float*)d_in[3];
    const float* Wg_b     = (const float*)d_in[4];
    const float* Wq_w     = (const float*)d_in[5];
    const float* Wq_b     = (const float*)d_in[6];
    const float* Wk_w     = (const float*)d_in[7];
    const float* Wk_b     = (const float*)d_in[8];
    float* out = (float*)d_out;

    // fused q/k GEMM: z=0 -> q = ref@WqT+bq, z=1 -> k = sup@WkT+bk
    gemm_nt_kernel<<<dim3(DDIM / BN, NDIM / BM, 2), 256>>>(
        ref_feat, Wq_w, Wq_b, sup_feat, Wk_w, Wk_b, DDIM, 1.0f, 0);
    // aff = (q @ kT) / 32
    gemm_nt_kernel<<<dim3(MDIM / BN, NDIM / BM, 1), 256>>>(
        nullptr, nullptr, nullptr, nullptr, nullptr, nullptr, MDIM, 0.03125f, 2);
    // pos stream + fused epilogue
    pos_epilogue_kernel<<<dim3(MDIM / 1024, NDIM), 256>>>(PE, Wg_w, Wg_b, out);
}